// round 2
// baseline (speedup 1.0000x reference)
#include <cuda_runtime.h>
#include <cstdint>

// ---------------------------------------------------------------------------
// HQNN: 3x (Dense+tanh -> 4-qubit RX/CNOT circuit).
// Analytic reformulation: each circuit output is multilinear in
// (cos a_v, sin a_v) over a fixed wire support T_w:
//   T0={0,1,3}, T1={0,2,3}, T2={1,3}, T3={0,2}
// Coefficients depend only on theta; extracted each launch by a tiny probe
// kernel (48 statevector sims), staged + memcpy'd into __constant__.
// ---------------------------------------------------------------------------

struct ConstsLayout {
    float C[3][16][4];   // probe table: C[layer][mask][wire]
    float W0[16][4];
    float b0[4];
    float W1[4][4];
    float b1[4];
    float W2[4][4];
    float b2[4];
};   // 300 floats = 1200 bytes

__device__ float g_stage[300];
__constant__ ConstsLayout cK;

// ------------------------- setup: probe simulations ------------------------

__device__ void rx_apply(float* re, float* im, float ang, int w) {
    float c = cosf(0.5f * ang);
    float s = sinf(0.5f * ang);
    int bit = 1 << w;
    for (int b = 0; b < 16; b++) {
        if (b & bit) continue;
        int b1 = b | bit;
        float r0 = re[b], i0 = im[b], r1 = re[b1], i1 = im[b1];
        re[b]  = c * r0 + s * i1;
        im[b]  = c * i0 - s * r1;
        re[b1] = c * r1 + s * i0;
        im[b1] = c * i1 - s * r0;
    }
}

__device__ void cnot_apply(float* re, float* im, int cw, int tw) {
    int cb = 1 << cw, tb = 1 << tw;
    for (int b = 0; b < 16; b++) {
        if ((b & cb) && !(b & tb)) {
            int b1 = b | tb;
            float t;
            t = re[b]; re[b] = re[b1]; re[b1] = t;
            t = im[b]; im[b] = im[b1]; im[b1] = t;
        }
    }
}

__global__ void hqnn_setup(const float* __restrict__ theta,
                           const float* __restrict__ W0, const float* __restrict__ b0,
                           const float* __restrict__ W1, const float* __restrict__ b1,
                           const float* __restrict__ W2, const float* __restrict__ b2) {
    int t = threadIdx.x;
    if (t < 48) {
        int l = t >> 4;      // hybrid layer 0..2
        int m = t & 15;      // probe mask over 4 wires
        float re[16], im[16];
        #pragma unroll
        for (int i = 0; i < 16; i++) { re[i] = 0.f; im[i] = 0.f; }
        re[0] = 1.f;
        // embedding RX with probe angles: pi/2 where mask bit set, else 0
        for (int w = 0; w < 4; w++) {
            float a = ((m >> w) & 1) ? 1.57079632679489662f : 0.0f;
            rx_apply(re, im, a, w);
        }
        // 2 entangler layers: RX(theta) per wire, then CNOT ring
        for (int e = 0; e < 2; e++) {
            for (int w = 0; w < 4; w++)
                rx_apply(re, im, theta[l * 8 + e * 4 + w], w);
            for (int w = 0; w < 4; w++)
                cnot_apply(re, im, w, (w + 1) & 3);
        }
        // Z expvals
        for (int w = 0; w < 4; w++) {
            float z = 0.f;
            for (int b = 0; b < 16; b++) {
                float p = re[b] * re[b] + im[b] * im[b];
                z += ((b >> w) & 1) ? -p : p;
            }
            g_stage[(l * 16 + m) * 4 + w] = z;
        }
    }
    // stage weights contiguously after the 192 coefficients
    for (int i = t; i < 108; i += blockDim.x) {
        float v;
        if (i < 64)       v = W0[i];
        else if (i < 68)  v = b0[i - 64];
        else if (i < 84)  v = W1[i - 68];
        else if (i < 88)  v = b1[i - 84];
        else if (i < 104) v = W2[i - 88];
        else              v = b2[i - 104];
        g_stage[192 + i] = v;
    }
}

// ------------------------------ main kernel --------------------------------

__device__ __forceinline__ float tanh_fast(float x) {
    float e = __expf(2.0f * x);
    return 1.0f - __fdividef(2.0f, e + 1.0f);
}

__device__ __forceinline__ void qcirc(const float (&C)[16][4],
                                      float a0, float a1, float a2, float a3,
                                      float& o0, float& o1, float& o2, float& o3) {
    float s0, c0, s1, c1, s2, c2, s3, c3;
    __sincosf(a0, &s0, &c0);
    __sincosf(a1, &s1, &c1);
    __sincosf(a2, &s2, &c2);
    __sincosf(a3, &s3, &c3);

    // out0: wires {0,1,3}; mask m = u0 + 2*u1 + 8*u3
    float p00 = c0 * c1, p10 = s0 * c1, p01 = c0 * s1, p11 = s0 * s1;
    float A  = C[0][0] * p00;
    A  = fmaf(C[1][0],  p10, A);
    A  = fmaf(C[2][0],  p01, A);
    A  = fmaf(C[3][0],  p11, A);
    float Bv = C[8][0] * p00;
    Bv = fmaf(C[9][0],  p10, Bv);
    Bv = fmaf(C[10][0], p01, Bv);
    Bv = fmaf(C[11][0], p11, Bv);
    o0 = fmaf(Bv, s3, A * c3);

    // out1: wires {0,2,3}; mask m = u0 + 4*u2 + 8*u3
    float q00 = c2 * c3, q10 = s2 * c3, q01 = c2 * s3, q11 = s2 * s3;
    A  = C[0][1] * q00;
    A  = fmaf(C[4][1],  q10, A);
    A  = fmaf(C[8][1],  q01, A);
    A  = fmaf(C[12][1], q11, A);
    Bv = C[1][1] * q00;
    Bv = fmaf(C[5][1],  q10, Bv);
    Bv = fmaf(C[9][1],  q01, Bv);
    Bv = fmaf(C[13][1], q11, Bv);
    o1 = fmaf(Bv, s0, A * c0);

    // out2: wires {1,3}; mask m = 2*u1 + 8*u3
    float r = C[0][2] * (c1 * c3);
    r = fmaf(C[2][2],  s1 * c3, r);
    r = fmaf(C[8][2],  c1 * s3, r);
    r = fmaf(C[10][2], s1 * s3, r);
    o2 = r;

    // out3: wires {0,2}; mask m = u0 + 4*u2
    float u = C[0][3] * (c0 * c2);
    u = fmaf(C[1][3], s0 * c2, u);
    u = fmaf(C[4][3], c0 * s2, u);
    u = fmaf(C[5][3], s0 * s2, u);
    o3 = u;
}

__global__ void __launch_bounds__(256) hqnn_main(const float* __restrict__ x,
                                                 float* __restrict__ out, int B) {
    int row = blockIdx.x * 256 + threadIdx.x;
    if (row >= B) return;

    const float4* xv = reinterpret_cast<const float4*>(x) + row * 4;
    float4 xa = xv[0];
    float4 xb = xv[1];
    float4 xc = xv[2];
    float4 xd = xv[3];

    // dense0 (16 -> 4) + tanh
    float h0, h1, h2, h3;
    {
        float acc[4];
        #pragma unroll
        for (int j = 0; j < 4; j++) {
            float a = cK.b0[j];
            a = fmaf(xa.x, cK.W0[0][j],  a);
            a = fmaf(xa.y, cK.W0[1][j],  a);
            a = fmaf(xa.z, cK.W0[2][j],  a);
            a = fmaf(xa.w, cK.W0[3][j],  a);
            a = fmaf(xb.x, cK.W0[4][j],  a);
            a = fmaf(xb.y, cK.W0[5][j],  a);
            a = fmaf(xb.z, cK.W0[6][j],  a);
            a = fmaf(xb.w, cK.W0[7][j],  a);
            a = fmaf(xc.x, cK.W0[8][j],  a);
            a = fmaf(xc.y, cK.W0[9][j],  a);
            a = fmaf(xc.z, cK.W0[10][j], a);
            a = fmaf(xc.w, cK.W0[11][j], a);
            a = fmaf(xd.x, cK.W0[12][j], a);
            a = fmaf(xd.y, cK.W0[13][j], a);
            a = fmaf(xd.z, cK.W0[14][j], a);
            a = fmaf(xd.w, cK.W0[15][j], a);
            acc[j] = a;
        }
        h0 = tanh_fast(acc[0]);
        h1 = tanh_fast(acc[1]);
        h2 = tanh_fast(acc[2]);
        h3 = tanh_fast(acc[3]);
    }

    float o0, o1, o2, o3;
    qcirc(cK.C[0], h0, h1, h2, h3, o0, o1, o2, o3);

    // dense1 (4 -> 4) + tanh
    {
        float acc[4];
        #pragma unroll
        for (int j = 0; j < 4; j++) {
            float a = cK.b1[j];
            a = fmaf(o0, cK.W1[0][j], a);
            a = fmaf(o1, cK.W1[1][j], a);
            a = fmaf(o2, cK.W1[2][j], a);
            a = fmaf(o3, cK.W1[3][j], a);
            acc[j] = a;
        }
        h0 = tanh_fast(acc[0]);
        h1 = tanh_fast(acc[1]);
        h2 = tanh_fast(acc[2]);
        h3 = tanh_fast(acc[3]);
    }

    qcirc(cK.C[1], h0, h1, h2, h3, o0, o1, o2, o3);

    // dense2 (4 -> 4) + tanh
    {
        float acc[4];
        #pragma unroll
        for (int j = 0; j < 4; j++) {
            float a = cK.b2[j];
            a = fmaf(o0, cK.W2[0][j], a);
            a = fmaf(o1, cK.W2[1][j], a);
            a = fmaf(o2, cK.W2[2][j], a);
            a = fmaf(o3, cK.W2[3][j], a);
            acc[j] = a;
        }
        h0 = tanh_fast(acc[0]);
        h1 = tanh_fast(acc[1]);
        h2 = tanh_fast(acc[2]);
        h3 = tanh_fast(acc[3]);
    }

    qcirc(cK.C[2], h0, h1, h2, h3, o0, o1, o2, o3);

    reinterpret_cast<float4*>(out)[row] = make_float4(o0, o1, o2, o3);
}

// ------------------------------ launch --------------------------------------

extern "C" void kernel_launch(void* const* d_in, const int* in_sizes, int n_in,
                              void* d_out, int out_size) {
    const float* x     = (const float*)d_in[0];
    const float* theta = (const float*)d_in[1];
    const float* W0    = (const float*)d_in[2];
    const float* b0    = (const float*)d_in[3];
    const float* W1    = (const float*)d_in[4];
    const float* b1    = (const float*)d_in[5];
    const float* W2    = (const float*)d_in[6];
    const float* b2    = (const float*)d_in[7];
    int B = in_sizes[0] / 16;

    hqnn_setup<<<1, 128>>>(theta, W0, b0, W1, b1, W2, b2);

    void* stage_ptr = nullptr;
    cudaGetSymbolAddress(&stage_ptr, g_stage);
    cudaMemcpyToSymbolAsync(cK, stage_ptr, sizeof(ConstsLayout), 0,
                            cudaMemcpyDeviceToDevice, 0);

    int blocks = (B + 255) / 256;
    hqnn_main<<<blocks, 256>>>(x, (float*)d_out, B);
}